// round 12
// baseline (speedup 1.0000x reference)
#include <cuda_runtime.h>
#include <cuda_fp16.h>

#define NN 40000
#define EE 640000
#define HD 128
#define GG 64
#define PADH 136   // padded halves per smem row (conflict-free ldmatrix)

// ---------------- scratch (no allocs: __device__ globals) -------------------
__device__ __align__(16) float  g_xw   [(size_t)NN * HD];  // x@W f32
__device__ __align__(16) __half g_xwh  [(size_t)NN * HD];  // x@W fp16 (gather)
__device__ __align__(16) __half g_aggh [(size_t)NN * HD];  // layer-1 edge accum
__device__ __align__(16) __half g_aggh2[(size_t)NN * HD];  // layer-2 edge accum
__device__ __align__(16) int    g_degi[NN];
__device__ __align__(16) float  g_dinv[NN];
__device__ __align__(16) int    g_src [EE];
__device__ __align__(16) int    g_dst [EE];
__device__ __align__(16) int    g_gstart[GG + 1];
__device__ __align__(16) float  g_pool[GG * HD];
__device__ int g_is64;

__device__ __forceinline__ int IDX(const void* p, long long pos) {
    return g_is64 ? (int)((const long long*)p)[pos] : ((const int*)p)[pos];
}

// ---------------- dtype detection (reads first 32KB only) -------------------
__global__ void detect_kernel(const unsigned int* __restrict__ raw) {
    __shared__ int nz;
    if (threadIdx.x == 0) nz = 0;
    __syncthreads();
    int cnt = 0;
    for (int j = threadIdx.x; j < 4096; j += 256)
        if (raw[2 * j + 1] != 0u) cnt++;
    atomicAdd(&nz, cnt);
    __syncthreads();
    if (threadIdx.x == 0) g_is64 = (nz < 64) ? 1 : 0;
}

// ---------------- prep ------------------------------------------------------
__global__ void zero_misc_kernel() {
    int i = blockIdx.x * blockDim.x + threadIdx.x;
    if (i < NN) g_degi[i] = 0;
    if (i <= GG) g_gstart[i] = NN;
    if (i < GG * HD) g_pool[i] = 0.f;
}

// index convert + in-degree histogram (NO 64-bin graph-count atomics)
__global__ void conv_deg_kernel(const void* __restrict__ ei) {
    int i = blockIdx.x * blockDim.x + threadIdx.x;
    if (i >= EE) return;
    int s = IDX(ei, i);
    int d = IDX(ei, (long long)EE + i);
    g_src[i] = s;
    g_dst[i] = d;
    atomicAdd(&g_degi[d], 1);
}

__global__ void dinv_kernel() {
    int i = blockIdx.x * blockDim.x + threadIdx.x;
    if (i < NN) g_dinv[i] = rsqrtf((float)g_degi[i] + 1.0f);
}

// graph boundaries from sorted batch (no atomics)
__global__ void gstart_kernel(const void* __restrict__ batch) {
    int i = blockIdx.x * blockDim.x + threadIdx.x;
    if (i >= NN) return;
    int b  = IDX(batch, i);
    int bp = i ? IDX(batch, i - 1) : -1;
    for (int g = bp + 1; g <= b; g++) g_gstart[g] = i;
}

// ---------------- tensor-core GEMM: C[M,128] = A[M,128] @ W[128,128] --------
// fused=1: A-tile computed inline as relu(aggh + xw*dinv^2 + bias) (layer-2)
__global__ __launch_bounds__(256) void gemm_tc_kernel(const float* __restrict__ A,
                                                      const float* __restrict__ W,
                                                      const float* __restrict__ bias,
                                                      int fused) {
    extern __shared__ __half smh[];
    __half* As = smh;                 // [128][PADH]
    __half* Bs = smh + 128 * PADH;    // [128][PADH]  (Bs[k][n])

    int tid = threadIdx.x;
    long long mbase = (long long)blockIdx.x * 128;

    if (!fused) {
#pragma unroll
        for (int i = 0; i < 16; i++) {
            int idx = i * 256 + tid;
            int row = idx >> 5, c4 = idx & 31;
            long long grow = mbase + row;
            float4 v = (grow < NN) ? ((const float4*)A)[grow * 32 + c4]
                                   : make_float4(0.f, 0.f, 0.f, 0.f);
            __half2* dst = (__half2*)(As + row * PADH + c4 * 4);
            dst[0] = __floats2half2_rn(v.x, v.y);
            dst[1] = __floats2half2_rn(v.z, v.w);
        }
    } else {
#pragma unroll
        for (int i = 0; i < 16; i++) {
            int idx = i * 256 + tid;
            int row = idx >> 5, c4 = idx & 31;
            long long grow = mbase + row;
            float4 h = make_float4(0.f, 0.f, 0.f, 0.f);
            if (grow < NN) {
                uint2 av = ((const uint2*)g_aggh)[grow * 32 + c4];
                float2 a0 = __half22float2(*(__half2*)&av.x);
                float2 a1 = __half22float2(*(__half2*)&av.y);
                float4 w = ((const float4*)g_xw)[grow * 32 + c4];
                float di = g_dinv[grow];
                float dd = di * di;
                float4 bb = ((const float4*)bias)[c4];
                h.x = fmaxf(fmaf(w.x, dd, a0.x) + bb.x, 0.f);
                h.y = fmaxf(fmaf(w.y, dd, a0.y) + bb.y, 0.f);
                h.z = fmaxf(fmaf(w.z, dd, a1.x) + bb.z, 0.f);
                h.w = fmaxf(fmaf(w.w, dd, a1.y) + bb.w, 0.f);
            }
            __half2* dst = (__half2*)(As + row * PADH + c4 * 4);
            dst[0] = __floats2half2_rn(h.x, h.y);
            dst[1] = __floats2half2_rn(h.z, h.w);
        }
    }
#pragma unroll
    for (int i = 0; i < 16; i++) {
        int idx = i * 256 + tid;
        int row = idx >> 5, c4 = idx & 31;
        float4 v = ((const float4*)W)[row * 32 + c4];
        __half2* dst = (__half2*)(Bs + row * PADH + c4 * 4);
        dst[0] = __floats2half2_rn(v.x, v.y);
        dst[1] = __floats2half2_rn(v.z, v.w);
    }
    __syncthreads();

    int wid = tid >> 5, lane = tid & 31;
    int wm = (wid & 3) * 32;
    int wn = (wid >> 2) * 64;

    float acc[2][8][4];
#pragma unroll
    for (int mt = 0; mt < 2; mt++)
#pragma unroll
        for (int nt = 0; nt < 8; nt++)
#pragma unroll
            for (int q = 0; q < 4; q++) acc[mt][nt][q] = 0.f;

#pragma unroll
    for (int kk = 0; kk < 8; kk++) {
        unsigned a[2][4];
#pragma unroll
        for (int mt = 0; mt < 2; mt++) {
            int r = lane & 15, c = (lane >> 4) * 8;
            unsigned addr = (unsigned)__cvta_generic_to_shared(
                As + (wm + mt * 16 + r) * PADH + kk * 16 + c);
            asm volatile("ldmatrix.sync.aligned.m8n8.x4.shared.b16 {%0,%1,%2,%3}, [%4];"
                         : "=r"(a[mt][0]), "=r"(a[mt][1]), "=r"(a[mt][2]), "=r"(a[mt][3])
                         : "r"(addr));
        }
        unsigned b[8][2];
#pragma unroll
        for (int nt2 = 0; nt2 < 4; nt2++) {
            int krow = kk * 16 + ((lane >> 3) & 1) * 8 + (lane & 7);
            int ncol = wn + nt2 * 16 + (lane >> 4) * 8;
            unsigned addr = (unsigned)__cvta_generic_to_shared(Bs + krow * PADH + ncol);
            asm volatile("ldmatrix.sync.aligned.m8n8.x4.trans.shared.b16 {%0,%1,%2,%3}, [%4];"
                         : "=r"(b[nt2 * 2][0]), "=r"(b[nt2 * 2][1]),
                           "=r"(b[nt2 * 2 + 1][0]), "=r"(b[nt2 * 2 + 1][1])
                         : "r"(addr));
        }
#pragma unroll
        for (int mt = 0; mt < 2; mt++)
#pragma unroll
            for (int nt = 0; nt < 8; nt++)
                asm volatile("mma.sync.aligned.m16n8k16.row.col.f32.f16.f16.f32 "
                             "{%0,%1,%2,%3}, {%4,%5,%6,%7}, {%8,%9}, {%0,%1,%2,%3};"
                             : "+f"(acc[mt][nt][0]), "+f"(acc[mt][nt][1]),
                               "+f"(acc[mt][nt][2]), "+f"(acc[mt][nt][3])
                             : "r"(a[mt][0]), "r"(a[mt][1]), "r"(a[mt][2]), "r"(a[mt][3]),
                               "r"(b[nt][0]), "r"(b[nt][1]));
    }

    int r0 = lane >> 2, cq = (lane & 3) * 2;
#pragma unroll
    for (int mt = 0; mt < 2; mt++) {
        long long rowA = mbase + wm + mt * 16 + r0;
        long long rowB = rowA + 8;
#pragma unroll
        for (int nt = 0; nt < 8; nt++) {
            int col = wn + nt * 8 + cq;
            if (rowA < NN) {
                *(float2*)&g_xw[rowA * HD + col] = make_float2(acc[mt][nt][0], acc[mt][nt][1]);
                *(__half2*)&g_xwh[rowA * HD + col] = __floats2half2_rn(acc[mt][nt][0], acc[mt][nt][1]);
            }
            if (rowB < NN) {
                *(float2*)&g_xw[rowB * HD + col] = make_float2(acc[mt][nt][2], acc[mt][nt][3]);
                *(__half2*)&g_xwh[rowB * HD + col] = __floats2half2_rn(acc[mt][nt][2], acc[mt][nt][3]);
            }
        }
    }
}

// ---------------- edge scatter: agg[dst] += xwh[src] * dinv[s]*dinv[d] ------
__global__ __launch_bounds__(256) void edge_kernel(__half* __restrict__ agg) {
    long long t = (long long)blockIdx.x * 256 + threadIdx.x;
    int e = (int)(t >> 4);
    if (e >= EE) return;
    int sub = threadIdx.x & 15;
    int s = g_src[e];
    int d = g_dst[e];
    float nm = __ldg(&g_dinv[s]) * __ldg(&g_dinv[d]);
    uint4 v = ((const uint4*)g_xwh)[(size_t)s * 16 + sub];
    __half2* hv = (__half2*)&v;
#pragma unroll
    for (int i = 0; i < 4; i++) {
        float2 f = __half22float2(hv[i]);
        hv[i] = __floats2half2_rn(f.x * nm, f.y * nm);
    }
    __half* p = agg + (size_t)d * HD + sub * 8;
    asm volatile("red.global.add.noftz.v4.f16x2 [%0], {%1,%2,%3,%4};"
                 :: "l"(p), "r"(v.x), "r"(v.y), "r"(v.z), "r"(v.w)
                 : "memory");
}

// ---------------- mean pool with fused layer-2 node epilogue ----------------
#define POOL_BLOCKS 320
#define POOL_NODES  125          // 320 * 125 = 40000
__global__ __launch_bounds__(128) void pool_accum_kernel(const void* __restrict__ batch,
                                                         const float* __restrict__ bias) {
    __shared__ float sh[GG * HD];        // 32 KB; thread t owns column t
    int t = threadIdx.x;
    for (int i = t; i < GG * HD; i += 128) sh[i] = 0.f;
    __syncthreads();
    float bb = bias[t];
    int start = blockIdx.x * POOL_NODES;
    for (int n = start; n < start + POOL_NODES; n++) {
        int g = IDX(batch, n);
        float a  = __half2float(g_aggh2[(size_t)n * HD + t]);
        float w  = g_xw[(size_t)n * HD + t];
        float di = g_dinv[n];
        float h  = fmaxf(fmaf(w, di * di, a) + bb, 0.f);
        sh[g * HD + t] += h;
    }
    __syncthreads();
    for (int i = t; i < GG * HD; i += 128) atomicAdd(&g_pool[i], sh[i]);
}

__global__ void pool_final_kernel(float* __restrict__ out) {
    int i = blockIdx.x * blockDim.x + threadIdx.x;
    if (i >= GG * HD) return;
    int g = i >> 7;
    float c = (float)(g_gstart[g + 1] - g_gstart[g]);
    out[i] = g_pool[i] / fmaxf(c, 1.0f);
}

// ---------------- launch -----------------------------------------------------
extern "C" void kernel_launch(void* const* d_in, const int* in_sizes, int n_in,
                              void* d_out, int out_size) {
    const float *x = 0, *W1 = 0, *b1 = 0, *W2 = 0, *b2 = 0;
    const void  *ei = 0, *batch = 0;
    for (int i = 0; i < n_in; i++) {
        long long sz = in_sizes[i];
        if      (sz == (long long)NN * HD) x = (const float*)d_in[i];
        else if (sz == 2LL * EE)           ei = d_in[i];
        else if (sz == NN)                 batch = d_in[i];
        else if (sz == HD * HD) { if (!W1) W1 = (const float*)d_in[i];
                                  else     W2 = (const float*)d_in[i]; }
        else if (sz == HD)      { if (!b1) b1 = (const float*)d_in[i];
                                  else     b2 = (const float*)d_in[i]; }
    }
    float* out = (float*)d_out;

    static cudaStream_t sA = 0;
    static cudaEvent_t ev0 = 0, ev1 = 0;
    static void* aggh_addr = 0;
    static void* aggh2_addr = 0;
    if (!sA) {
        cudaStreamCreateWithFlags(&sA, cudaStreamNonBlocking);
        cudaEventCreateWithFlags(&ev0, cudaEventDisableTiming);
        cudaEventCreateWithFlags(&ev1, cudaEventDisableTiming);
        cudaGetSymbolAddress(&aggh_addr, g_aggh);
        cudaGetSymbolAddress(&aggh2_addr, g_aggh2);
        cudaFuncSetAttribute((const void*)gemm_tc_kernel,
                             cudaFuncAttributeMaxDynamicSharedMemorySize,
                             2 * 128 * PADH * (int)sizeof(__half));
    }

    const int ZBM   = (NN + 255) / 256;       // 157
    const int EB    = (EE + 255) / 256;       // 2500
    const int EDGB  = (EE * 16) / 256;        // 40000
    const int GEMMB = (NN + 127) / 128;       // 313
    const int GSM   = 2 * 128 * PADH * (int)sizeof(__half);
    const size_t AGG_BYTES = (size_t)NN * HD * sizeof(__half);

    // fork: sA does both memsets + GEMM1 + gstart; main does the rest of prep
    cudaEventRecord(ev0, 0);
    cudaStreamWaitEvent(sA, ev0, 0);
    cudaMemsetAsync(aggh_addr,  0, AGG_BYTES, sA);
    cudaMemsetAsync(aggh2_addr, 0, AGG_BYTES, sA);
    gemm_tc_kernel<<<GEMMB, 256, GSM, sA>>>(x, W1, 0, 0);
    cudaEventRecord(ev1, sA);

    detect_kernel<<<1, 256>>>((const unsigned int*)ei);
    zero_misc_kernel<<<ZBM, 256>>>();
    conv_deg_kernel<<<EB, 256>>>(ei);
    dinv_kernel<<<ZBM, 256>>>();
    gstart_kernel<<<ZBM, 256>>>(batch);

    // join: layer-1 edge phase into g_aggh
    cudaStreamWaitEvent(0, ev1, 0);
    edge_kernel<<<EDGB, 256>>>((__half*)aggh_addr);

    // GEMM2 with fused node-1 epilogue (reads g_aggh/g_xw/g_dinv/b1)
    gemm_tc_kernel<<<GEMMB, 256, GSM>>>(0, W2, b1, 1);

    // layer-2 edge phase into g_aggh2 (already zeroed)
    edge_kernel<<<EDGB, 256>>>((__half*)aggh2_addr);

    // pool with fused node-2 epilogue
    pool_accum_kernel<<<POOL_BLOCKS, 128>>>(batch, b2);
    pool_final_kernel<<<(GG * HD + 255) / 256, 256>>>(out);
}